// round 16
// baseline (speedup 1.0000x reference)
#include <cuda_runtime.h>
#include <cuda_bf16.h>
#include <math_constants.h>

#define NPARTS 24
#define MAXB   64
#define MAXN   16384
#define MAXC   128
#define XSLOTS 16    // xyz blocks per batch (2 warp-partials each -> 32 slots/batch)
#define PACKB  256   // pack blocks at the head of the grid

// __device__ scratch (allocation-free; zero-initialized at module load)
__device__ unsigned int g_labels8[(MAXB * MAXN) / 4];   // u8-packed labels
// xyz partials: [b][k][slot 0..31][comp 0..3]
__device__ float g_partf[MAXB * NPARTS * 32 * 4];
__device__ float g_counts[MAXB * NPARTS];               // denominators
// monotonic sync state (NEVER reset — replay-safe by modular/threshold tests)
__device__ int   g_pack_done;                           // += 1 per pack block
__device__ int   g_xyz_arrive[MAXB];                    // += 1 per xyz block
__device__ int   g_cnt_epoch[MAXB];                     // += 1 per finalize

// ---------------------------------------------------------------------------
// ONE kernel, 64-thread blocks, 12 KB smem:
//   [0, PACKB)            pack labels -> u8
//   [PACKB, +B*XSLOTS)    xyz partials; LAST arriver per batch finalizes
//                         counts + mean_xyz (writes out[0..2])
//   [PACKB+B*XSLOTS, ...) feat core (pair scheme, u8 labels, depth-2,
//                         NH=1: full N per warp) -> writes mean/surface
//                         directly to out. No merge kernel.
// Low block IDs (pack, xyz) are scheduled first -> spins cannot deadlock.
// Counters are monotonic so every graph replay does identical work.
// ---------------------------------------------------------------------------
#define RMW1(f, k) do {                               \
    float2 _v = ap[(k) * 32];                         \
    _v.x += (f); _v.y = fmaxf(_v.y, (f));             \
    ap[(k) * 32] = _v;                                \
} while (0)

#define RMW4(f, q) do {                               \
    RMW1((f).x, (q) & 255);                           \
    RMW1((f).y, ((q) >> 8) & 255);                    \
    RMW1((f).z, ((q) >> 16) & 255);                   \
    RMW1((f).w, (q) >> 24);                           \
} while (0)

__global__ __launch_bounds__(64) void fused_kernel(
    const float* __restrict__ features, const float* __restrict__ xyz,
    const int* __restrict__ labels, float* __restrict__ out,
    int N, int C, int B)
{
    const int w    = threadIdx.x >> 5;
    const int lane = threadIdx.x & 31;
    const int outd = 3 + 2 * C;

    __shared__ float4 acc4[2][NPARTS][16];            // 12 KB
    __shared__ int    s_flag;

    if (blockIdx.x < PACKB) {
        // ---------------- pack path ----------------
        const int BN4 = (B * N) >> 2;
        const int T   = PACKB * 64;
        const int4* __restrict__ l4 = (const int4*)labels;
        for (int i = blockIdx.x * 64 + threadIdx.x; i < BN4; i += T) {
            const int4 li = l4[i];
            g_labels8[i] = (unsigned)li.x | ((unsigned)li.y << 8) |
                           ((unsigned)li.z << 16) | ((unsigned)li.w << 24);
        }
        __threadfence();                              // release stores
        __syncthreads();
        if (threadIdx.x == 0)
            atomicAdd(&g_pack_done, 1);
        return;
    }

    const int XYZB = B * XSLOTS;
    if (blockIdx.x < PACKB + XYZB) {
        // ---------------- xyz path (component scheme, raw labels) ----------
        const int g = lane >> 2;
        const int c = lane & 3;
        float* accf = (float*)&acc4[w][0][0];         // [k*64 + lane]
        #pragma unroll
        for (int k = 0; k < NPARTS; ++k)
            accf[k * 64 + lane] = 0.f;
        __syncwarp();

        const int xb    = blockIdx.x - PACKB;
        const int b     = xb / XSLOTS;
        const int s     = xb % XSLOTS;
        const int chunk = N / XSLOTS;                 // 1024 points per block
        const int base  = b * N + s * chunk + w * (chunk >> 1);
        const int iters = chunk >> 4;                 // 8 points per warp-iter

        int   pt   = base + g;
        int   lab0 = labels[pt];
        float v0   = (c < 3) ? xyz[3 * pt + c] : 1.0f;

        for (int i = 0; i < iters - 1; ++i) {
            const int ptn  = base + (i + 1) * 8 + g;
            const int   lab1 = labels[ptn];
            const float v1   = (c < 3) ? xyz[3 * ptn + c] : 1.0f;
            accf[lab0 * 64 + lane] += v0;
            lab0 = lab1; v0 = v1;
        }
        accf[lab0 * 64 + lane] += v0;
        __syncwarp();

        const int slotInB = s * 2 + w;                // 0..31 within batch
        for (int k = 0; k < NPARTS; ++k) {
            float v = accf[k * 64 + lane];
            v += __shfl_xor_sync(0xFFFFFFFFu, v, 4);
            v += __shfl_xor_sync(0xFFFFFFFFu, v, 8);
            v += __shfl_xor_sync(0xFFFFFFFFu, v, 16);
            if (lane < 4)
                g_partf[(((size_t)(b * NPARTS + k)) * 32 + slotInB) * 4 + c] = v;
        }

        // arrive; last block of this batch (this replay) finalizes counts
        __threadfence();
        __syncthreads();
        if (threadIdx.x == 0) {
            const int old = atomicAdd(&g_xyz_arrive[b], 1);
            s_flag = ((old + 1) % XSLOTS == 0);
        }
        __syncthreads();
        if (s_flag) {
            // reduce 32 slots for 12 k's per warp; coalesced 512 B reads
            for (int j = 0; j < NPARTS / 2; ++j) {
                const int k = w * (NPARTS / 2) + j;
                float4 v = *(const float4*)
                    &g_partf[(((size_t)(b * NPARTS + k)) * 32 + lane) * 4];
                #pragma unroll
                for (int off = 16; off; off >>= 1) {
                    v.x += __shfl_xor_sync(0xFFFFFFFFu, v.x, off);
                    v.y += __shfl_xor_sync(0xFFFFFFFFu, v.y, off);
                    v.z += __shfl_xor_sync(0xFFFFFFFFu, v.z, off);
                    v.w += __shfl_xor_sync(0xFFFFFFFFu, v.w, off);
                }
                if (lane == 0) {
                    const float denom = fmaxf(v.w, 1.f);
                    g_counts[b * NPARTS + k] = denom;
                    float* o = out + (size_t)(b * NPARTS + k) * outd;
                    o[0] = v.x / denom;
                    o[1] = v.y / denom;
                    o[2] = v.z / denom;
                }
            }
            __threadfence();                          // release counts
            __syncthreads();
            if (threadIdx.x == 0)
                atomicAdd(&g_cnt_epoch[b], 1);
        }
        return;
    }

    // ---------------- feat path (pair scheme, NH=1: full N per warp) -------
    const int pair = lane >> 1;
    const int odd  = lane & 1;
    const int gwid = (blockIdx.x - PACKB - XYZB) * 2 + w;
    const int b  = gwid >> 6;                         // tasks_per_b = C/2 = 64
    const int cp = gwid & 63;                         // channel pair

    float2* ap = (float2*)((char*)(&acc4[w][0][0]) + pair * 16 + odd * 8);
    #pragma unroll
    for (int k = 0; k < NPARTS; ++k)
        ap[k * 32] = make_float2(0.f, -CUDART_INF_F);

    const int c = cp * 2 + odd;
    const float4* __restrict__ fr =
        (const float4*)features + ((size_t)(b * C + c) * (N >> 2));
    const unsigned* __restrict__ lr = g_labels8 + (((size_t)b * N) >> 2);

    const int iters = N >> 6;                         // 16 words/warp-iter, full N

    // prefetch label-independent feature loads BEFORE the pack spin
    float4 f0 = __ldcs(&fr[pair]);
    float4 f1 = __ldcs(&fr[16 + pair]);

    if (threadIdx.x == 0) {                           // wait for packing
        while (*(volatile int*)&g_pack_done < PACKB)
            __nanosleep(128);
    }
    __syncthreads();
    __threadfence();                                  // acquire

    unsigned q0 = lr[pair];
    unsigned q1 = lr[16 + pair];

    for (int i = 0; i < iters - 2; ++i) {
        const int nb = (i + 2) * 16 + pair;
        const float4   f2 = __ldcs(&fr[nb]);
        const unsigned q2 = lr[nb];
        RMW4(f0, q0);
        f0 = f1; q0 = q1; f1 = f2; q1 = q2;
    }
    RMW4(f0, q0);
    RMW4(f1, q1);
    __syncwarp();

    // wait for this batch's counts (xyz finished ~100us ago; effectively free)
    if (threadIdx.x == 0) {
        while (*(volatile int*)&g_cnt_epoch[b] < 1)
            __nanosleep(128);
    }
    __syncthreads();
    __threadfence();                                  // acquire counts

    for (int k = 0; k < NPARTS; ++k) {
        float2 v = ap[k * 32];
        #pragma unroll
        for (int off = 2; off < 32; off <<= 1) {
            v.x += __shfl_xor_sync(0xFFFFFFFFu, v.x, off);
            v.y = fmaxf(v.y, __shfl_xor_sync(0xFFFFFFFFu, v.y, off));
        }
        if (lane < 2) {   // lane0 -> channel c, lane1 -> channel c+1
            const float denom = g_counts[b * NPARTS + k];
            const float mean  = v.x / denom;
            float* o = out + (size_t)(b * NPARTS + k) * outd;
            o[3 + c]     = mean;
            o[3 + C + c] = fmaxf(v.y - mean, 0.f);    // empty seg: -inf -> 0
        }
    }
}

extern "C" void kernel_launch(void* const* d_in, const int* in_sizes, int n_in,
                              void* d_out, int out_size)
{
    const float* xyz      = (const float*)d_in[0];
    const float* features = (const float*)d_in[1];
    const int*   labels   = (const int*)d_in[2];
    float* out = (float*)d_out;

    const long long BN = in_sizes[2];                  // B*N
    const int C = (int)((long long)in_sizes[1] / BN);  // 128
    const int outd = 3 + 2 * C;                        // 259
    const int B = out_size / (NPARTS * outd);          // 64
    const int N = (int)(BN / B);                       // 16384

    const int xyz_blocks  = B * XSLOTS;                // 1024
    const int feat_blocks = B * (C / 2) / 2;           // 2048
    fused_kernel<<<PACKB + xyz_blocks + feat_blocks, 64>>>(
        features, xyz, labels, out, N, C, B);
}

// round 17
// speedup vs baseline: 1.1518x; 1.1518x over previous
#include <cuda_runtime.h>
#include <cuda_bf16.h>
#include <math_constants.h>

#define NPARTS 24
#define MAXB   64
#define MAXN   16384
#define MAXC   128
#define XSLOTS 16    // xyz blocks per batch (2 warp-partials each -> 32 slots/batch)
#define NH     2     // n-halves per channel-pair (both land in ONE feat block)
#define PACKB  256   // pack blocks at the head of the grid

// __device__ scratch (allocation-free; zero-initialized at module load)
__device__ unsigned int g_labels8[(MAXB * MAXN) / 4];   // u8-packed labels
// xyz partials: [b][k][slot 0..31][comp 0..3]
__device__ float g_partf[MAXB * NPARTS * 32 * 4];
__device__ float g_counts[MAXB * NPARTS];               // denominators
// monotonic sync state (NEVER reset — replay-safe threshold/modular tests)
__device__ int   g_pack_done;                           // += 1 per pack block
__device__ int   g_xyz_arrive[MAXB];                    // += 1 per xyz block
__device__ int   g_cnt_epoch[MAXB];                     // += 1 per finalize

// ---------------------------------------------------------------------------
// ONE kernel, 64-thread blocks, 12 KB smem (19 blocks/SM):
//   [0, PACKB)            pack labels -> u8
//   [PACKB, +B*XSLOTS)    xyz partials; LAST arriver per batch finalizes
//                         counts + mean_xyz (writes out[0..2])
//   [PACKB+B*XSLOTS, ...) R15 feat core (pair scheme, u8 labels, depth-2,
//                         NH=2). KEY: warps 0/1 of each feat block are the
//                         two n-halves of the SAME (b, channel pair), so the
//                         cross-half combine is one __syncthreads() away —
//                         merge kernel deleted, outputs written here.
// Low block IDs (pack, xyz) schedule first -> spins cannot deadlock.
// ---------------------------------------------------------------------------
#define RMW1(f, k) do {                               \
    float2 _v = ap[(k) * 32];                         \
    _v.x += (f); _v.y = fmaxf(_v.y, (f));             \
    ap[(k) * 32] = _v;                                \
} while (0)

#define RMW4(f, q) do {                               \
    RMW1((f).x, (q) & 255);                           \
    RMW1((f).y, ((q) >> 8) & 255);                    \
    RMW1((f).z, ((q) >> 16) & 255);                   \
    RMW1((f).w, (q) >> 24);                           \
} while (0)

__global__ __launch_bounds__(64) void fused_kernel(
    const float* __restrict__ features, const float* __restrict__ xyz,
    const int* __restrict__ labels, float* __restrict__ out,
    int N, int C, int B)
{
    const int w    = threadIdx.x >> 5;
    const int lane = threadIdx.x & 31;
    const int outd = 3 + 2 * C;

    __shared__ float4 acc4[2][NPARTS][16];            // 12 KB (all paths)
    __shared__ int    s_flag;

    if (blockIdx.x < PACKB) {
        // ---------------- pack path ----------------
        const int BN4 = (B * N) >> 2;
        const int T   = PACKB * 64;
        const int4* __restrict__ l4 = (const int4*)labels;
        for (int i = blockIdx.x * 64 + threadIdx.x; i < BN4; i += T) {
            const int4 li = l4[i];
            g_labels8[i] = (unsigned)li.x | ((unsigned)li.y << 8) |
                           ((unsigned)li.z << 16) | ((unsigned)li.w << 24);
        }
        __threadfence();                              // release stores
        __syncthreads();
        if (threadIdx.x == 0)
            atomicAdd(&g_pack_done, 1);
        return;
    }

    const int XYZB = B * XSLOTS;
    if (blockIdx.x < PACKB + XYZB) {
        // ---------------- xyz path (component scheme, raw labels) ----------
        const int g = lane >> 2;
        const int c = lane & 3;
        float* accf = (float*)&acc4[w][0][0];         // [k*64 + lane]
        #pragma unroll
        for (int k = 0; k < NPARTS; ++k)
            accf[k * 64 + lane] = 0.f;
        __syncwarp();

        const int xb    = blockIdx.x - PACKB;
        const int b     = xb / XSLOTS;
        const int s     = xb % XSLOTS;
        const int chunk = N / XSLOTS;                 // 1024 points per block
        const int base  = b * N + s * chunk + w * (chunk >> 1);
        const int iters = chunk >> 4;                 // 8 points per warp-iter

        int   pt   = base + g;
        int   lab0 = labels[pt];
        float v0   = (c < 3) ? xyz[3 * pt + c] : 1.0f;

        for (int i = 0; i < iters - 1; ++i) {
            const int ptn  = base + (i + 1) * 8 + g;
            const int   lab1 = labels[ptn];
            const float v1   = (c < 3) ? xyz[3 * ptn + c] : 1.0f;
            accf[lab0 * 64 + lane] += v0;
            lab0 = lab1; v0 = v1;
        }
        accf[lab0 * 64 + lane] += v0;
        __syncwarp();

        const int slotInB = s * 2 + w;                // 0..31 within batch
        for (int k = 0; k < NPARTS; ++k) {
            float v = accf[k * 64 + lane];
            v += __shfl_xor_sync(0xFFFFFFFFu, v, 4);
            v += __shfl_xor_sync(0xFFFFFFFFu, v, 8);
            v += __shfl_xor_sync(0xFFFFFFFFu, v, 16);
            if (lane < 4)
                g_partf[(((size_t)(b * NPARTS + k)) * 32 + slotInB) * 4 + c] = v;
        }

        // arrive; last block of this batch (this replay) finalizes counts
        __threadfence();
        __syncthreads();
        if (threadIdx.x == 0) {
            const int old = atomicAdd(&g_xyz_arrive[b], 1);
            s_flag = ((old + 1) % XSLOTS == 0);
        }
        __syncthreads();
        if (s_flag) {
            for (int j = 0; j < NPARTS / 2; ++j) {
                const int k = w * (NPARTS / 2) + j;
                float4 v = *(const float4*)
                    &g_partf[(((size_t)(b * NPARTS + k)) * 32 + lane) * 4];
                #pragma unroll
                for (int off = 16; off; off >>= 1) {
                    v.x += __shfl_xor_sync(0xFFFFFFFFu, v.x, off);
                    v.y += __shfl_xor_sync(0xFFFFFFFFu, v.y, off);
                    v.z += __shfl_xor_sync(0xFFFFFFFFu, v.z, off);
                    v.w += __shfl_xor_sync(0xFFFFFFFFu, v.w, off);
                }
                if (lane == 0) {
                    const float denom = fmaxf(v.w, 1.f);
                    g_counts[b * NPARTS + k] = denom;
                    float* o = out + (size_t)(b * NPARTS + k) * outd;
                    o[0] = v.x / denom;
                    o[1] = v.y / denom;
                    o[2] = v.z / denom;
                }
            }
            __threadfence();                          // release counts
            __syncthreads();
            if (threadIdx.x == 0)
                atomicAdd(&g_cnt_epoch[b], 1);
        }
        return;
    }

    // ---------------- feat path (R15 core, NH=2) ----------------
    const int pair = lane >> 1;
    const int odd  = lane & 1;
    const int tasks_per_b = (C / 2) * NH;             // 128
    const int gwid = (blockIdx.x - PACKB - XYZB) * 2 + w;
    const int b  = gwid / tasks_per_b;
    const int r  = gwid % tasks_per_b;
    const int cp = r >> 1;                            // same for both warps
    const int h  = r & 1;                             // w=0 -> h=0, w=1 -> h=1

    float2* ap = (float2*)((char*)(&acc4[w][0][0]) + pair * 16 + odd * 8);
    #pragma unroll
    for (int k = 0; k < NPARTS; ++k)
        ap[k * 32] = make_float2(0.f, -CUDART_INF_F);

    const int c = cp * 2 + odd;
    const float4* __restrict__ fr =
        (const float4*)features + ((size_t)(b * C + c) * (N >> 2));
    const unsigned* __restrict__ lr = g_labels8 + (((size_t)b * N) >> 2);

    const int half4 = N >> 3;                         // float4 words per half
    const int base  = h * half4;
    const int iters = half4 >> 4;                     // 16 words per warp-iter

    // prefetch label-independent feature loads BEFORE the pack spin
    float4 f0 = __ldcs(&fr[base + pair]);
    float4 f1 = __ldcs(&fr[base + 16 + pair]);

    if (threadIdx.x == 0) {                           // wait for packing
        while (*(volatile int*)&g_pack_done < PACKB)
            __nanosleep(128);
    }
    __syncthreads();
    __threadfence();                                  // acquire

    unsigned q0 = lr[base + pair];
    unsigned q1 = lr[base + 16 + pair];

    for (int i = 0; i < iters - 2; ++i) {
        const int nb = base + (i + 2) * 16 + pair;
        const float4   f2 = __ldcs(&fr[nb]);
        const unsigned q2 = lr[nb];
        RMW4(f0, q0);
        f0 = f1; q0 = q1; f1 = f2; q1 = q2;
    }
    RMW4(f0, q0);
    RMW4(f1, q1);
    __syncwarp();

    // per-warp totals; park them in cell k's storage (already consumed)
    for (int k = 0; k < NPARTS; ++k) {
        float2 v = ap[k * 32];
        #pragma unroll
        for (int off = 2; off < 32; off <<= 1) {
            v.x += __shfl_xor_sync(0xFFFFFFFFu, v.x, off);
            v.y = fmaxf(v.y, __shfl_xor_sync(0xFFFFFFFFu, v.y, off));
        }
        if (lane < 2)   // lane0 -> channel c0 total, lane1 -> channel c0+1
            ((float2*)&acc4[w][k][0])[lane] = v;
    }
    __syncthreads();

    // warp 0 combines the two halves and writes final outputs
    if (w == 0) {
        if (lane == 0) {   // counts finished ~100us ago; effectively free
            while (*(volatile int*)&g_cnt_epoch[b] < 1)
                __nanosleep(64);
        }
        __syncwarp();
        __threadfence();                              // acquire counts

        for (int t = lane; t < 2 * NPARTS; t += 32) {
            const int k  = t >> 1;
            const int c2 = t & 1;
            const float2 v0 = ((float2*)&acc4[0][k][0])[c2];
            const float2 v1 = ((float2*)&acc4[1][k][0])[c2];
            const float s = v0.x + v1.x;
            const float m = fmaxf(v0.y, v1.y);
            const float denom = g_counts[b * NPARTS + k];
            const float mean = s / denom;
            float* o = out + (size_t)(b * NPARTS + k) * outd;
            o[3 + 2 * cp + c2]     = mean;
            o[3 + C + 2 * cp + c2] = fmaxf(m - mean, 0.f);  // empty seg -> 0
        }
    }
}

extern "C" void kernel_launch(void* const* d_in, const int* in_sizes, int n_in,
                              void* d_out, int out_size)
{
    const float* xyz      = (const float*)d_in[0];
    const float* features = (const float*)d_in[1];
    const int*   labels   = (const int*)d_in[2];
    float* out = (float*)d_out;

    const long long BN = in_sizes[2];                  // B*N
    const int C = (int)((long long)in_sizes[1] / BN);  // 128
    const int outd = 3 + 2 * C;                        // 259
    const int B = out_size / (NPARTS * outd);          // 64
    const int N = (int)(BN / B);                       // 16384

    const int xyz_blocks  = B * XSLOTS;                // 1024
    const int feat_blocks = B * (C / 2) * NH / 2;      // 4096
    fused_kernel<<<PACKB + xyz_blocks + feat_blocks, 64>>>(
        features, xyz, labels, out, N, C, B);
}